// round 2
// baseline (speedup 1.0000x reference)
#include <cuda_runtime.h>

#define BB 64
#define NN 2048
#define DIM 768
#define POOL 1024
#define PLEN 16
#define ROWS 32              // rows per copy/mean block
#define CHUNKS (NN / ROWS)   // 64 partial chunks per batch
#define OUTROWS (2 * PLEN + NN)  // 2080
#define EPS 1e-12f

// Static device scratch (no allocation allowed in kernel_launch)
__device__ float g_partial[BB * CHUNKS * DIM];   // 12.6 MB chunked row-sums
__device__ float g_xnorm[BB * DIM];
__device__ float g_rk1[POOL];                    // 1/||prompt_key[p]||
__device__ float g_rk2[POOL];                    // 1/||residual_prompt_key[p]||
__device__ int   g_idx[BB];
__device__ int   g_residx[BB];
__device__ float g_accum;

// ---------------------------------------------------------------------------
// Kernel A: stream x_embed -> out rows [32, 2080) while accumulating
// deterministic per-chunk column sums for the mean-pool.
// grid = BB*CHUNKS blocks, 768 threads (one thread per channel).
// ---------------------------------------------------------------------------
__global__ __launch_bounds__(DIM) void copy_mean_kernel(
    const float* __restrict__ x, float* __restrict__ out)
{
    int blk = blockIdx.x;
    int b = blk / CHUNKS;
    int k = blk % CHUNKS;
    int c = threadIdx.x;

    const float* src = x   + ((size_t)b * NN + (size_t)k * ROWS) * DIM + c;
    float*       dst = out + ((size_t)b * OUTROWS + 2 * PLEN + (size_t)k * ROWS) * DIM + c;

    float s = 0.f;
    #pragma unroll 8
    for (int r = 0; r < ROWS; r++) {
        float v = src[(size_t)r * DIM];
        s += v;
        dst[(size_t)r * DIM] = v;
    }
    g_partial[((size_t)b * CHUNKS + k) * DIM + c] = s;
}

// ---------------------------------------------------------------------------
// Kernel B: inverse L2 norms of the two key pools. grid = 2*POOL blocks.
// ---------------------------------------------------------------------------
__global__ __launch_bounds__(256) void keynorm_kernel(
    const float* __restrict__ pkey, const float* __restrict__ rkey)
{
    int row = blockIdx.x;
    const float* src;
    float* dst;
    if (row < POOL) { src = pkey + (size_t)row * DIM;          dst = g_rk1 + row; }
    else            { src = rkey + (size_t)(row - POOL) * DIM; dst = g_rk2 + (row - POOL); }

    int tid = threadIdx.x;
    float s = 0.f;
    for (int c = tid; c < DIM; c += 256) { float v = src[c]; s += v * v; }

    __shared__ float red[256];
    red[tid] = s;
    __syncthreads();
    for (int o = 128; o >= 1; o >>= 1) {
        if (tid < o) red[tid] += red[tid + o];
        __syncthreads();
    }
    if (tid == 0) *dst = rsqrtf(fmaxf(red[0], EPS));
}

// ---------------------------------------------------------------------------
// Kernel C: reduce chunked partials -> x_mean -> x_norm (deterministic order).
// grid = BB blocks, 768 threads. Also zeroes the pull-loss accumulator.
// ---------------------------------------------------------------------------
__global__ __launch_bounds__(DIM) void xnorm_kernel()
{
    int b = blockIdx.x;
    int c = threadIdx.x;

    float s = 0.f;
    #pragma unroll 8
    for (int k = 0; k < CHUNKS; k++)
        s += g_partial[((size_t)b * CHUNKS + k) * DIM + c];
    float mean = s * (1.0f / NN);

    __shared__ float red[DIM];
    red[c] = mean * mean;
    __syncthreads();
    if (c < 256) red[c] += red[c + 512];   // fold 768 -> 512
    __syncthreads();
    for (int o = 256; o >= 1; o >>= 1) {
        if (c < o) red[c] += red[c + o];
        __syncthreads();
    }
    float inv = rsqrtf(fmaxf(red[0], EPS));
    g_xnorm[(size_t)b * DIM + c] = mean * inv;

    if (b == 0 && c == 0) g_accum = 0.f;
}

// ---------------------------------------------------------------------------
// Kernel D: per-batch two-level top-1 selection + pull-loss accumulation.
// grid = BB blocks, 256 threads (8 warps; warp w owns p ≡ w mod 8).
// Tie-break: lowest index (matches jax.lax.top_k stability).
// ---------------------------------------------------------------------------
__global__ __launch_bounds__(256) void select_kernel(
    const float* __restrict__ pkey, const float* __restrict__ rkey)
{
    int b = blockIdx.x;
    int tid = threadIdx.x;
    int lane = tid & 31;
    int w = tid >> 5;

    __shared__ float xs[DIM];
    __shared__ float resv[DIM];
    __shared__ float bw[8];
    __shared__ int   bi[8];
    __shared__ float s_m1;
    __shared__ int   s_idx;

    for (int c = tid; c < DIM; c += 256) xs[c] = g_xnorm[(size_t)b * DIM + c];
    __syncthreads();

    // pass 1: argmax_p  (x_norm . prompt_key[p]) * rk1[p]
    float best = -1e30f; int bestp = 0;
    for (int p = w; p < POOL; p += 8) {
        const float* kp = pkey + (size_t)p * DIM;
        float s = 0.f;
        for (int c = lane; c < DIM; c += 32) s += xs[c] * kp[c];
        #pragma unroll
        for (int o = 16; o; o >>= 1) s += __shfl_xor_sync(0xffffffffu, s, o);
        s *= g_rk1[p];
        if (s > best) { best = s; bestp = p; }
    }
    if (lane == 0) { bw[w] = best; bi[w] = bestp; }
    __syncthreads();
    if (tid == 0) {
        float m = bw[0]; int mi = bi[0];
        #pragma unroll
        for (int i = 1; i < 8; i++)
            if (bw[i] > m || (bw[i] == m && bi[i] < mi)) { m = bw[i]; mi = bi[i]; }
        s_m1 = m; s_idx = mi; g_idx[b] = mi;
    }
    __syncthreads();

    // residual = prompt_key[idx] - x_norm
    int id = s_idx;
    for (int c = tid; c < DIM; c += 256)
        resv[c] = pkey[(size_t)id * DIM + c] - xs[c];
    __syncthreads();

    // pass 2: argmax_p  (residual . residual_prompt_key[p]) * rk2[p]
    best = -1e30f; bestp = 0;
    for (int p = w; p < POOL; p += 8) {
        const float* kp = rkey + (size_t)p * DIM;
        float s = 0.f;
        for (int c = lane; c < DIM; c += 32) s += resv[c] * kp[c];
        #pragma unroll
        for (int o = 16; o; o >>= 1) s += __shfl_xor_sync(0xffffffffu, s, o);
        s *= g_rk2[p];
        if (s > best) { best = s; bestp = p; }
    }
    if (lane == 0) { bw[w] = best; bi[w] = bestp; }
    __syncthreads();
    if (tid == 0) {
        float m = bw[0]; int mi = bi[0];
        #pragma unroll
        for (int i = 1; i < 8; i++)
            if (bw[i] > m || (bw[i] == m && bi[i] < mi)) { m = bw[i]; mi = bi[i]; }
        g_residx[b] = mi;
        atomicAdd(&g_accum, (s_m1 + m) * (1.0f / BB));
    }
}

// ---------------------------------------------------------------------------
// Kernel E: gather selected prompt tiles into out rows [0,32), write scalar.
// grid = BB blocks, 768 threads.
// ---------------------------------------------------------------------------
__global__ __launch_bounds__(DIM) void gather_kernel(
    const float* __restrict__ prompt, const float* __restrict__ rprompt,
    float* __restrict__ out, int write_scalar, size_t scalar_off)
{
    int b = blockIdx.x;
    int c = threadIdx.x;
    int id1 = g_idx[b];
    int id2 = g_residx[b];

    const float* src1 = rprompt + (size_t)id2 * PLEN * DIM;  // rows 0..15
    const float* src2 = prompt  + (size_t)id1 * PLEN * DIM;  // rows 16..31
    float* dst = out + (size_t)b * OUTROWS * DIM;

    #pragma unroll
    for (int r = 0; r < PLEN; r++) {
        dst[(size_t)r * DIM + c]            = src1[(size_t)r * DIM + c];
        dst[(size_t)(PLEN + r) * DIM + c]   = src2[(size_t)r * DIM + c];
    }

    if (write_scalar && b == 0 && c == 0) out[scalar_off] = g_accum;
}

// ---------------------------------------------------------------------------
extern "C" void kernel_launch(void* const* d_in, const int* in_sizes, int n_in,
                              void* d_out, int out_size)
{
    const float* x       = (const float*)d_in[0];
    const float* prompt  = (const float*)d_in[1];
    const float* pkey    = (const float*)d_in[2];
    const float* rprompt = (const float*)d_in[3];
    const float* rkey    = (const float*)d_in[4];
    float* out = (float*)d_out;

    copy_mean_kernel<<<BB * CHUNKS, DIM>>>(x, out);
    keynorm_kernel<<<2 * POOL, 256>>>(pkey, rkey);
    xnorm_kernel<<<BB, DIM>>>();
    select_kernel<<<BB, 256>>>(pkey, rkey);

    long long prompted_elems = (long long)BB * OUTROWS * DIM;  // 102,236,160
    int write_scalar = ((long long)out_size > prompted_elems) ? 1 : 0;
    gather_kernel<<<BB, DIM>>>(prompt, rprompt, out, write_scalar,
                               (size_t)prompted_elems);
}

// round 8
// speedup vs baseline: 2.9615x; 2.9615x over previous
#include <cuda_runtime.h>

#define BB 64
#define NN 2048
#define DIM 768
#define D4 (DIM / 4)             // 192 float4 per row
#define POOL 1024
#define PLEN 16
#define ROWS 32                  // rows per copy/mean block
#define CHUNKS (NN / ROWS)       // 64 partial chunks per batch
#define OUTROWS (2 * PLEN + NN)  // 2080
#define EPS 1e-12f

// Static device scratch — referenced ONLY from device code.
__device__ float4 g_partial[BB * CHUNKS * D4];   // 12.6 MB chunked row-sums
__device__ float4 g_xnorm[BB * D4];
__device__ float4 g_res[BB * D4];
__device__ float  g_scores1[BB * POOL];
__device__ float  g_scores2[BB * POOL];
__device__ float  g_m1[BB];
__device__ int    g_idx[BB];
__device__ int    g_residx[BB];
__device__ float  g_accum;

// ---------------------------------------------------------------------------
// A: stream x_embed -> out rows [32,2080) via float4, accumulating per-chunk
// column sums. grid = BB*CHUNKS (4096), block = 192 (one float4 lane each).
// ---------------------------------------------------------------------------
__global__ __launch_bounds__(D4) void copy_mean_kernel(
    const float4* __restrict__ x, float4* __restrict__ out)
{
    int blk = blockIdx.x;
    int b = blk / CHUNKS;
    int k = blk % CHUNKS;
    int c = threadIdx.x;

    const float4* src = x   + ((size_t)b * NN + (size_t)k * ROWS) * D4 + c;
    float4*       dst = out + ((size_t)b * OUTROWS + 2 * PLEN + (size_t)k * ROWS) * D4 + c;

    float4 s = make_float4(0.f, 0.f, 0.f, 0.f);
    #pragma unroll 8
    for (int r = 0; r < ROWS; r++) {
        float4 v = src[(size_t)r * D4];
        s.x += v.x; s.y += v.y; s.z += v.z; s.w += v.w;
        dst[(size_t)r * D4] = v;
    }
    g_partial[((size_t)b * CHUNKS + k) * D4 + c] = s;
}

// ---------------------------------------------------------------------------
// B: reduce chunked partials -> mean -> x_norm. grid = BB, block = 192.
// Also zeroes the pull-loss accumulator.
// ---------------------------------------------------------------------------
__global__ __launch_bounds__(D4) void xnorm_kernel()
{
    int b = blockIdx.x;
    int c = threadIdx.x;

    float4 s = make_float4(0.f, 0.f, 0.f, 0.f);
    #pragma unroll 8
    for (int k = 0; k < CHUNKS; k++) {
        float4 v = g_partial[((size_t)b * CHUNKS + k) * D4 + c];
        s.x += v.x; s.y += v.y; s.z += v.z; s.w += v.w;
    }
    const float inv_n = 1.0f / NN;
    float4 m = make_float4(s.x * inv_n, s.y * inv_n, s.z * inv_n, s.w * inv_n);

    __shared__ float red[D4];
    red[c] = m.x * m.x + m.y * m.y + m.z * m.z + m.w * m.w;
    __syncthreads();
    if (c < 64) red[c] += red[c + 64] + red[c + 128];
    __syncthreads();
    for (int o = 32; o >= 1; o >>= 1) {
        if (c < o) red[c] += red[c + o];
        __syncthreads();
    }
    float inv = rsqrtf(fmaxf(red[0], EPS));
    g_xnorm[(size_t)b * D4 + c] = make_float4(m.x * inv, m.y * inv, m.z * inv, m.w * inv);

    if (b == 0 && c == 0) g_accum = 0.f;
}

// ---------------------------------------------------------------------------
// C: similarity GEMV — one block per pool entry. Loads the key row into smem,
// computes its inverse L2 norm in-block, then dots against all 64 query rows.
// pass=0: keys=prompt_key,  queries=g_xnorm, out=g_scores1
// pass=1: keys=residual_key, queries=g_res,  out=g_scores2
// grid = POOL (1024), block = 256 (8 warps x 8 batches each).
// ---------------------------------------------------------------------------
__global__ __launch_bounds__(256) void sim_kernel(
    const float4* __restrict__ keys, int pass)
{
    int p = blockIdx.x;
    int tid = threadIdx.x;
    int lane = tid & 31;
    int w = tid >> 5;

    __shared__ float4 kk[D4];
    __shared__ float red[64];
    __shared__ float s_scale;

    if (tid < D4) kk[tid] = keys[(size_t)p * D4 + tid];
    __syncthreads();

    // in-block key inverse-norm (deterministic fixed-order reduction)
    {
        float s = 0.f;
        #pragma unroll
        for (int j = 0; j < 3; j++) {           // 256 threads? no: use first 64
            ;
        }
        if (tid < 64) {
            s = 0.f;
            #pragma unroll
            for (int j = 0; j < 3; j++) {
                float4 v = kk[tid + j * 64];
                s += v.x * v.x + v.y * v.y + v.z * v.z + v.w * v.w;
            }
            red[tid] = s;
        }
        __syncthreads();
        if (tid < 32) red[tid] += red[tid + 32];
        __syncthreads();
        if (tid < 16) red[tid] += red[tid + 16];
        __syncthreads();
        if (tid < 8)  red[tid] += red[tid + 8];
        __syncthreads();
        if (tid < 4)  red[tid] += red[tid + 4];
        __syncthreads();
        if (tid == 0) s_scale = rsqrtf(fmaxf(red[0] + red[1] + red[2] + red[3], EPS));
        __syncthreads();
    }
    float scale = s_scale;

    const float4* xbase = (pass == 0) ? g_xnorm : g_res;
    float* scores = (pass == 0) ? g_scores1 : g_scores2;

    #pragma unroll
    for (int bi = 0; bi < 8; bi++) {
        int b = w * 8 + bi;
        const float4* xr = xbase + (size_t)b * D4;
        float s = 0.f;
        #pragma unroll
        for (int j = 0; j < 6; j++) {
            int c = lane + j * 32;
            float4 a = xr[c];
            float4 k = kk[c];
            s += a.x * k.x + a.y * k.y + a.z * k.z + a.w * k.w;
        }
        #pragma unroll
        for (int o = 16; o; o >>= 1) s += __shfl_xor_sync(0xffffffffu, s, o);
        if (lane == 0) scores[(size_t)b * POOL + p] = s * scale;
    }
}

// ---------------------------------------------------------------------------
// D: argmax over g_scores1 (lowest-index tie-break) + residual computation.
// grid = BB, block = 256.
// ---------------------------------------------------------------------------
__global__ __launch_bounds__(256) void argmax1_kernel(const float* __restrict__ pkey)
{
    int b = blockIdx.x;
    int tid = threadIdx.x;

    float best = -1e30f; int bestp = POOL;
    #pragma unroll
    for (int j = 0; j < POOL / 256; j++) {
        int p = tid + j * 256;
        float v = g_scores1[(size_t)b * POOL + p];
        if (v > best || (v == best && p < bestp)) { best = v; bestp = p; }
    }

    __shared__ float bv[256];
    __shared__ int   bp[256];
    bv[tid] = best; bp[tid] = bestp;
    __syncthreads();
    for (int o = 128; o >= 1; o >>= 1) {
        if (tid < o) {
            float v = bv[tid + o]; int p = bp[tid + o];
            if (v > bv[tid] || (v == bv[tid] && p < bp[tid])) { bv[tid] = v; bp[tid] = p; }
        }
        __syncthreads();
    }
    if (tid == 0) { g_idx[b] = bp[0]; g_m1[b] = bv[0]; }
    __syncthreads();

    int id = bp[0];
    const float* kp = pkey + (size_t)id * DIM;
    const float* xn = (const float*)&g_xnorm[(size_t)b * D4];
    float* rs = (float*)&g_res[(size_t)b * D4];
    for (int c = tid; c < DIM; c += 256)
        rs[c] = kp[c] - xn[c];
}

// ---------------------------------------------------------------------------
// E: argmax over g_scores2 + pull-loss accumulation. grid = BB, block = 256.
// ---------------------------------------------------------------------------
__global__ __launch_bounds__(256) void argmax2_kernel()
{
    int b = blockIdx.x;
    int tid = threadIdx.x;

    float best = -1e30f; int bestp = POOL;
    #pragma unroll
    for (int j = 0; j < POOL / 256; j++) {
        int p = tid + j * 256;
        float v = g_scores2[(size_t)b * POOL + p];
        if (v > best || (v == best && p < bestp)) { best = v; bestp = p; }
    }

    __shared__ float bv[256];
    __shared__ int   bp[256];
    bv[tid] = best; bp[tid] = bestp;
    __syncthreads();
    for (int o = 128; o >= 1; o >>= 1) {
        if (tid < o) {
            float v = bv[tid + o]; int p = bp[tid + o];
            if (v > bv[tid] || (v == bv[tid] && p < bp[tid])) { bv[tid] = v; bp[tid] = p; }
        }
        __syncthreads();
    }
    if (tid == 0) {
        g_residx[b] = bp[0];
        atomicAdd(&g_accum, (g_m1[b] + bv[0]) * (1.0f / BB));
    }
}

// ---------------------------------------------------------------------------
// F: gather selected prompt tiles into out rows [0,32), write scalar.
// grid = BB, block = 192 (float4 lanes).
// ---------------------------------------------------------------------------
__global__ __launch_bounds__(D4) void gather_kernel(
    const float4* __restrict__ prompt, const float4* __restrict__ rprompt,
    float4* __restrict__ out, int write_scalar, size_t scalar_off)
{
    int b = blockIdx.x;
    int c = threadIdx.x;
    int id1 = g_idx[b];
    int id2 = g_residx[b];

    const float4* src1 = rprompt + (size_t)id2 * PLEN * D4;  // rows 0..15
    const float4* src2 = prompt  + (size_t)id1 * PLEN * D4;  // rows 16..31
    float4* dst = out + (size_t)b * OUTROWS * D4;

    #pragma unroll
    for (int r = 0; r < PLEN; r++) {
        dst[(size_t)r * D4 + c]          = src1[(size_t)r * D4 + c];
        dst[(size_t)(PLEN + r) * D4 + c] = src2[(size_t)r * D4 + c];
    }

    if (write_scalar && b == 0 && c == 0)
        ((float*)out)[scalar_off] = g_accum;
}

// ---------------------------------------------------------------------------
extern "C" void kernel_launch(void* const* d_in, const int* in_sizes, int n_in,
                              void* d_out, int out_size)
{
    const float4* x       = (const float4*)d_in[0];
    const float4* prompt  = (const float4*)d_in[1];
    const float4* pkey4   = (const float4*)d_in[2];
    const float4* rprompt = (const float4*)d_in[3];
    const float4* rkey4   = (const float4*)d_in[4];
    float4* out = (float4*)d_out;

    copy_mean_kernel<<<BB * CHUNKS, D4>>>(x, out);
    xnorm_kernel<<<BB, D4>>>();
    sim_kernel<<<POOL, 256>>>(pkey4, 0);
    argmax1_kernel<<<BB, 256>>>((const float*)pkey4);
    sim_kernel<<<POOL, 256>>>(rkey4, 1);
    argmax2_kernel<<<BB, 256>>>();

    long long prompted_elems = (long long)BB * OUTROWS * DIM;  // 102,236,160
    int write_scalar = ((long long)out_size > prompted_elems) ? 1 : 0;
    gather_kernel<<<BB, D4>>>(prompt, rprompt, out, write_scalar,
                              (size_t)prompted_elems);
}

// round 9
// speedup vs baseline: 3.0909x; 1.0437x over previous
#include <cuda_runtime.h>

#define BB 64
#define NN 2048
#define DIM 768
#define D4 (DIM / 4)             // 192 float4 per row
#define POOL 1024
#define PLEN 16
#define ROWS 128                 // rows per copy/mean block
#define CHUNKS (NN / ROWS)       // 16 partial chunks per batch
#define OUTROWS (2 * PLEN + NN)  // 2080
#define KPB 8                    // keys per sim block
#define NBLK (POOL / KPB)        // 128 sim blocks
#define EPS 1e-12f

// Static device scratch — referenced ONLY from device code.
__device__ float4 g_partial[BB * CHUNKS * D4];   // 3.1 MB chunked row-sums
__device__ float4 g_xnorm[BB * D4];
__device__ float4 g_res[BB * D4];
__device__ float2 g_part1[BB * NBLK];            // (val, idx-bits) partial argmax
__device__ float2 g_part2[BB * NBLK];
__device__ float  g_m1[BB];
__device__ int    g_idx[BB];
__device__ float  g_accum;
__device__ unsigned int g_count;

// ---------------------------------------------------------------------------
// A: stream x_embed -> out rows [32,2080) via float4, accumulating per-chunk
// column sums. grid = BB*CHUNKS (1024), block = 192 (one float4 lane each).
// ---------------------------------------------------------------------------
__global__ __launch_bounds__(D4) void copy_mean_kernel(
    const float4* __restrict__ x, float4* __restrict__ out)
{
    int blk = blockIdx.x;
    int b = blk / CHUNKS;
    int k = blk % CHUNKS;
    int c = threadIdx.x;

    const float4* src = x   + ((size_t)b * NN + (size_t)k * ROWS) * D4 + c;
    float4*       dst = out + ((size_t)b * OUTROWS + 2 * PLEN + (size_t)k * ROWS) * D4 + c;

    float4 s = make_float4(0.f, 0.f, 0.f, 0.f);
    #pragma unroll 8
    for (int r = 0; r < ROWS; r++) {
        float4 v = src[(size_t)r * D4];
        s.x += v.x; s.y += v.y; s.z += v.z; s.w += v.w;
        dst[(size_t)r * D4] = v;
    }
    g_partial[((size_t)b * CHUNKS + k) * D4 + c] = s;
}

// ---------------------------------------------------------------------------
// B: reduce chunked partials -> mean -> x_norm. grid = BB, block = 192.
// Also zeroes the pull-loss accumulator and ticket counter.
// ---------------------------------------------------------------------------
__global__ __launch_bounds__(D4) void xnorm_kernel()
{
    int b = blockIdx.x;
    int c = threadIdx.x;

    float4 s = make_float4(0.f, 0.f, 0.f, 0.f);
    #pragma unroll
    for (int k = 0; k < CHUNKS; k++) {
        float4 v = g_partial[((size_t)b * CHUNKS + k) * D4 + c];
        s.x += v.x; s.y += v.y; s.z += v.z; s.w += v.w;
    }
    const float inv_n = 1.0f / NN;
    float4 m = make_float4(s.x * inv_n, s.y * inv_n, s.z * inv_n, s.w * inv_n);

    __shared__ float red[D4];
    red[c] = m.x * m.x + m.y * m.y + m.z * m.z + m.w * m.w;
    __syncthreads();
    if (c < 64) red[c] += red[c + 64] + red[c + 128];
    __syncthreads();
    for (int o = 32; o >= 1; o >>= 1) {
        if (c < o) red[c] += red[c + o];
        __syncthreads();
    }
    float inv = rsqrtf(fmaxf(red[0], EPS));
    g_xnorm[(size_t)b * D4 + c] = make_float4(m.x * inv, m.y * inv, m.z * inv, m.w * inv);

    if (b == 0 && c == 0) { g_accum = 0.f; g_count = 0u; }
}

// ---------------------------------------------------------------------------
// C: similarity + per-block partial argmax. grid = NBLK (128), block = 256.
// Block blk owns keys [blk*8, blk*8+8): loads them into smem, computes their
// inverse norms, then each warp w handles batches [w*8, w*8+8): query row in
// registers, 8 key-dots from smem, running lowest-index argmax.
// pass=0: queries=g_xnorm -> g_part1;  pass=1: queries=g_res -> g_part2.
// ---------------------------------------------------------------------------
__global__ __launch_bounds__(256) void sim_kernel(
    const float4* __restrict__ keys, int pass)
{
    int blk = blockIdx.x;
    int tid = threadIdx.x;
    int lane = tid & 31;
    int w = tid >> 5;

    __shared__ float4 kk[KPB][D4];     // 24 KB
    __shared__ float  inv[KPB];

    for (int i = tid; i < KPB * D4; i += 256) {
        int kr = i / D4, cc = i % D4;
        kk[kr][cc] = keys[((size_t)blk * KPB + kr) * D4 + cc];
    }
    __syncthreads();

    // warp w computes inverse norm of key w
    {
        float s = 0.f;
        #pragma unroll
        for (int j = 0; j < 6; j++) {
            float4 v = kk[w][lane + j * 32];
            s += v.x * v.x + v.y * v.y + v.z * v.z + v.w * v.w;
        }
        #pragma unroll
        for (int o = 16; o; o >>= 1) s += __shfl_xor_sync(0xffffffffu, s, o);
        if (lane == 0) inv[w] = rsqrtf(fmaxf(s, EPS));
    }
    __syncthreads();

    const float4* xbase = (pass == 0) ? g_xnorm : g_res;
    float2* part = (pass == 0) ? g_part1 : g_part2;

    #pragma unroll
    for (int bi = 0; bi < 8; bi++) {
        int b = w * 8 + bi;
        const float4* xr = xbase + (size_t)b * D4;
        float4 q[6];
        #pragma unroll
        for (int j = 0; j < 6; j++) q[j] = xr[lane + j * 32];

        float best = -1e30f; int bp = 0;
        #pragma unroll
        for (int kr = 0; kr < KPB; kr++) {
            float s = 0.f;
            #pragma unroll
            for (int j = 0; j < 6; j++) {
                float4 k = kk[kr][lane + j * 32];
                s += q[j].x * k.x + q[j].y * k.y + q[j].z * k.z + q[j].w * k.w;
            }
            #pragma unroll
            for (int o = 16; o; o >>= 1) s += __shfl_xor_sync(0xffffffffu, s, o);
            s *= inv[kr];
            if (s > best) { best = s; bp = blk * KPB + kr; }  // ascending -> lowest idx on tie
        }
        if (lane == 0) {
            float2 pr; pr.x = best; pr.y = __int_as_float(bp);
            part[(size_t)b * NBLK + blk] = pr;
        }
    }
}

// ---------------------------------------------------------------------------
// D: final argmax over g_part1 (lowest-index tie-break) + residual.
// grid = BB, block = 128.
// ---------------------------------------------------------------------------
__global__ __launch_bounds__(128) void final1_kernel(const float* __restrict__ pkey)
{
    int b = blockIdx.x;
    int tid = threadIdx.x;

    __shared__ float bv[128];
    __shared__ int   bp[128];

    float2 pr = g_part1[(size_t)b * NBLK + tid];
    bv[tid] = pr.x; bp[tid] = __float_as_int(pr.y);
    __syncthreads();
    for (int o = 64; o >= 1; o >>= 1) {
        if (tid < o) {
            float v = bv[tid + o]; int p = bp[tid + o];
            if (v > bv[tid] || (v == bv[tid] && p < bp[tid])) { bv[tid] = v; bp[tid] = p; }
        }
        __syncthreads();
    }
    if (tid == 0) { g_idx[b] = bp[0]; g_m1[b] = bv[0]; }

    int id = bp[0];
    const float* kp = pkey + (size_t)id * DIM;
    const float* xn = (const float*)&g_xnorm[(size_t)b * D4];
    float* rs = (float*)&g_res[(size_t)b * D4];
    #pragma unroll
    for (int j = 0; j < DIM / 128; j++) {
        int c = tid + j * 128;
        rs[c] = kp[c] - xn[c];
    }
}

// ---------------------------------------------------------------------------
// E: final argmax over g_part2 + pull-loss + fused prompt gather + scalar.
// grid = BB, block = 256.
// ---------------------------------------------------------------------------
__global__ __launch_bounds__(256) void final2_kernel(
    const float4* __restrict__ prompt, const float4* __restrict__ rprompt,
    float4* __restrict__ out, int write_scalar, size_t scalar_off)
{
    int b = blockIdx.x;
    int tid = threadIdx.x;

    __shared__ float bv[128];
    __shared__ int   bp[128];

    if (tid < 128) {
        float2 pr = g_part2[(size_t)b * NBLK + tid];
        bv[tid] = pr.x; bp[tid] = __float_as_int(pr.y);
    }
    __syncthreads();
    for (int o = 64; o >= 1; o >>= 1) {
        if (tid < o) {
            float v = bv[tid + o]; int p = bp[tid + o];
            if (v > bv[tid] || (v == bv[tid] && p < bp[tid])) { bv[tid] = v; bp[tid] = p; }
        }
        __syncthreads();
    }
    int id2 = bp[0];
    int id1 = g_idx[b];

    // fused gather: rows [0,16) = residual prompt tile, [16,32) = prompt tile
    const float4* src1 = rprompt + (size_t)id2 * PLEN * D4;
    const float4* src2 = prompt  + (size_t)id1 * PLEN * D4;
    float4* dst = out + (size_t)b * OUTROWS * D4;

    const int TOT = PLEN * D4;                 // 3072 float4 per tile
    #pragma unroll
    for (int j = 0; j < TOT / 256; j++) {      // 12 iterations
        int i = tid + j * 256;
        dst[i]       = src1[i];
        dst[TOT + i] = src2[i];
    }

    if (tid == 0) {
        atomicAdd(&g_accum, (g_m1[b] + bv[0]) * (1.0f / BB));
        __threadfence();
        unsigned int old = atomicAdd(&g_count, 1u);
        if (write_scalar && old == BB - 1) {
            float total = atomicAdd(&g_accum, 0.f);   // ordered read
            ((float*)out)[scalar_off] = total;
        }
    }
}

// ---------------------------------------------------------------------------
extern "C" void kernel_launch(void* const* d_in, const int* in_sizes, int n_in,
                              void* d_out, int out_size)
{
    const float4* x       = (const float4*)d_in[0];
    const float4* prompt  = (const float4*)d_in[1];
    const float4* pkey4   = (const float4*)d_in[2];
    const float4* rprompt = (const float4*)d_in[3];
    const float4* rkey4   = (const float4*)d_in[4];
    float4* out = (float4*)d_out;

    copy_mean_kernel<<<BB * CHUNKS, D4>>>(x, out);
    xnorm_kernel<<<BB, D4>>>();
    sim_kernel<<<NBLK, 256>>>(pkey4, 0);
    final1_kernel<<<BB, 128>>>((const float*)pkey4);
    sim_kernel<<<NBLK, 256>>>(rkey4, 1);

    long long prompted_elems = (long long)BB * OUTROWS * DIM;  // 102,236,160
    int write_scalar = ((long long)out_size > prompted_elems) ? 1 : 0;
    final2_kernel<<<BB, 256>>>(prompt, rprompt, out, write_scalar,
                               (size_t)prompted_elems);
}